// round 1
// baseline (speedup 1.0000x reference)
#include <cuda_runtime.h>
#include <cfloat>

// Problem constants
#define BB 4
#define NN 8
#define GG 32          // BB*NN
#define LL 2048
#define EE 16384
#define C0 128
#define CC 256
#define PARTS 256

// ---------------- scratch (device globals; no allocation allowed) ----------------
__device__ __align__(16) float g_bufX [(size_t)GG*LL*CC];   // activations, LC layout [g][l][c]
__device__ __align__(16) float g_bufHW[(size_t)GG*LL*CC];   // gemm output  [g][l][co]
__device__ __align__(16) float g_bufAG[(size_t)GG*LL*CC];   // aggregated   [g][l][co]
__device__ __align__(16) float g_xp   [(size_t)BB*LL*CC];   // pooled       [b][l][c]
__device__ __align__(16) float g_hws  [(size_t)BB*LL*CC];
__device__ __align__(16) float g_aggs [(size_t)BB*LL*CC];

__device__ float g_deg[LL];
__device__ float g_dis[LL];
__device__ float g_selfw[LL];
__device__ int   g_cnt[LL];
__device__ int   g_rowptr[LL+1];
__device__ int   g_col[EE];
__device__ float g_w[EE];

__device__ __align__(16) float g_part [PARTS*2*CC];
__device__ __align__(16) float g_parts[PARTS*2*CC];
__device__ __align__(16) float g_scale1[CC], g_shift1[CC], g_scale2[CC], g_shift2[CC];

// ---------------- graph preprocessing ----------------
__global__ void k_zero_graph() {
    int i = blockIdx.x*blockDim.x + threadIdx.x;
    if (i < LL) { g_deg[i] = 0.f; g_cnt[i] = 0; }
}

__global__ void k_deg(const int* __restrict__ ei) {
    int e = blockIdx.x*blockDim.x + threadIdx.x;
    if (e < EE) {
        int dst = ei[EE + e];
        atomicAdd(&g_deg[dst], 1.0f);   // sum of 1.0f's: exact, order-independent
        atomicAdd(&g_cnt[dst], 1);
    }
}

__global__ void k_dis() {
    int i = blockIdx.x*blockDim.x + threadIdx.x;
    if (i < LL) {
        float d = g_deg[i] + 2.0f;      // improved=True self weight 2.0
        float r = rsqrtf(d);
        g_dis[i] = r;
        g_selfw[i] = 2.0f * r * r;
    }
}

// exclusive scan of g_cnt -> g_rowptr (single block, Hillis-Steele, deterministic)
__global__ void k_scan() {
    __shared__ int s[2][LL];
    int t = threadIdx.x;
    s[0][t]        = g_cnt[t];
    s[0][t + 1024] = g_cnt[t + 1024];
    __syncthreads();
    int cur = 0;
    for (int off = 1; off < LL; off <<= 1) {
        int nxt = cur ^ 1;
        for (int i = t; i < LL; i += 1024) {
            int v = s[cur][i];
            if (i >= off) v += s[cur][i - off];
            s[nxt][i] = v;
        }
        __syncthreads();
        cur = nxt;
    }
    for (int i = t; i < LL; i += 1024) g_rowptr[i + 1] = s[cur][i];
    if (t == 0) g_rowptr[0] = 0;
}

// fill CSR: one warp per dst node, stable order over the edge list (deterministic)
__global__ void k_fill(const int* __restrict__ ei) {
    int wid  = (blockIdx.x*blockDim.x + threadIdx.x) >> 5;
    int lane = threadIdx.x & 31;
    if (wid >= LL) return;
    int node = wid;
    int base = g_rowptr[node];
    float dn = g_dis[node];
    int count = 0;
    for (int e0 = 0; e0 < EE; e0 += 32) {       // EE % 32 == 0
        int e = e0 + lane;
        int d = ei[EE + e];
        bool m = (d == node);
        unsigned mask = __ballot_sync(0xffffffffu, m);
        if (m) {
            int rank = __popc(mask & ((1u << lane) - 1u));
            int s = ei[e];
            g_col[base + count + rank] = s;
            g_w  [base + count + rank] = g_dis[s] * dn;
        }
        count += __popc(mask);
    }
}

// ---------------- layout transforms ----------------
// x input [g][ci][l] -> g_bufX [g][l][ci]  (Cin = C0)
__global__ void k_transpose_in(const float* __restrict__ x) {
    __shared__ float tile[32][33];
    int g = blockIdx.z;
    int l0 = blockIdx.x * 32, c0 = blockIdx.y * 32;
    int tx = threadIdx.x, ty = threadIdx.y;
    const float* src = x + (size_t)g * C0 * LL;
    #pragma unroll
    for (int i = ty; i < 32; i += 8)
        tile[i][tx] = src[(size_t)(c0 + i) * LL + l0 + tx];
    __syncthreads();
    float* dstp = g_bufX + (size_t)g * LL * C0;
    #pragma unroll
    for (int i = ty; i < 32; i += 8)
        dstp[(size_t)(l0 + i) * C0 + c0 + tx] = tile[tx][i];
}

// g_bufX [g][l][c] -> out [g][c][l]   (C = CC)
__global__ void k_transpose_out(float* __restrict__ out) {
    __shared__ float tile[32][33];
    int g = blockIdx.z;
    int l0 = blockIdx.x * 32, c0 = blockIdx.y * 32;
    int tx = threadIdx.x, ty = threadIdx.y;
    #pragma unroll
    for (int i = ty; i < 32; i += 8)
        tile[i][tx] = g_bufX[((size_t)g * LL + l0 + i) * CC + c0 + tx];
    __syncthreads();
    #pragma unroll
    for (int i = ty; i < 32; i += 8)
        out[((size_t)g * CC + c0 + i) * LL + l0 + tx] = tile[tx][i];
}

// pooled max over n: g_xp[b][l][c] = max_n g_bufX[(b*NN+n)][l][c]
__global__ void k_pool(int Cin) {
    int idx = blockIdx.x*blockDim.x + threadIdx.x;
    int tot = BB * LL * Cin;
    if (idx >= tot) return;
    int per = LL * Cin;
    int b = idx / per;
    int rem = idx - b * per;
    const float* base = g_bufX + (size_t)b * NN * per;
    float m = -FLT_MAX;
    #pragma unroll
    for (int n = 0; n < NN; n++)
        m = fmaxf(m, base[(size_t)n * per + rem]);
    g_xp[idx] = m;
}

// ---------------- GEMM: C[M,256] = A[M,K] * W[K,256], row-major, fp32 ----------------
__global__ __launch_bounds__(256) void k_gemm(const float* __restrict__ A,
                                              const float* __restrict__ Bw,
                                              float* __restrict__ Cc,
                                              int M, int K) {
    __shared__ float As[8][128];
    __shared__ float Bs[8][128];
    int n0 = blockIdx.x * 128;
    int m0 = blockIdx.y * 128;
    int tid = threadIdx.x;
    int tx = tid & 15, ty = tid >> 4;
    int la_m = tid >> 1, la_k = (tid & 1) * 4;
    int lb_k = tid >> 5, lb_n = (tid & 31) * 4;

    float acc[8][8];
    #pragma unroll
    for (int i = 0; i < 8; i++)
        #pragma unroll
        for (int j = 0; j < 8; j++) acc[i][j] = 0.f;

    for (int k0 = 0; k0 < K; k0 += 8) {
        float4 av = *(const float4*)(A + (size_t)(m0 + la_m) * K + k0 + la_k);
        As[la_k + 0][la_m] = av.x;
        As[la_k + 1][la_m] = av.y;
        As[la_k + 2][la_m] = av.z;
        As[la_k + 3][la_m] = av.w;
        float4 bv = *(const float4*)(Bw + (size_t)(k0 + lb_k) * CC + n0 + lb_n);
        *(float4*)&Bs[lb_k][lb_n] = bv;
        __syncthreads();
        #pragma unroll
        for (int k = 0; k < 8; k++) {
            float a[8], b[8];
            *(float4*)(a)     = *(const float4*)&As[k][ty * 8];
            *(float4*)(a + 4) = *(const float4*)&As[k][ty * 8 + 4];
            *(float4*)(b)     = *(const float4*)&Bs[k][tx * 8];
            *(float4*)(b + 4) = *(const float4*)&Bs[k][tx * 8 + 4];
            #pragma unroll
            for (int i = 0; i < 8; i++)
                #pragma unroll
                for (int j = 0; j < 8; j++)
                    acc[i][j] = fmaf(a[i], b[j], acc[i][j]);
        }
        __syncthreads();
    }
    #pragma unroll
    for (int i = 0; i < 8; i++) {
        float* cp = Cc + (size_t)(m0 + ty * 8 + i) * CC + n0 + tx * 8;
        *(float4*)(cp)     = make_float4(acc[i][0], acc[i][1], acc[i][2], acc[i][3]);
        *(float4*)(cp + 4) = make_float4(acc[i][4], acc[i][5], acc[i][6], acc[i][7]);
    }
}

// ---------------- SpMM: agg[g][dst][:] = selfw*hw[g][dst] + sum_e w_e*hw[g][src_e] + bias ----------------
__global__ void k_spmm(const float* __restrict__ hw, float* __restrict__ agg,
                       const float* __restrict__ bias, int Gc) {
    int wid  = (blockIdx.x*blockDim.x + threadIdx.x) >> 5;
    int lane = threadIdx.x & 31;
    if (wid >= Gc * LL) return;
    int g = wid / LL, dst = wid - g * LL;
    const float* rowbase = hw + (size_t)g * LL * CC;
    float acc[8];
    {
        float w = g_selfw[dst];
        const float4* r = (const float4*)(rowbase + (size_t)dst * CC);
        float4 v0 = r[lane], v1 = r[lane + 32];
        acc[0] = w * v0.x; acc[1] = w * v0.y; acc[2] = w * v0.z; acc[3] = w * v0.w;
        acc[4] = w * v1.x; acc[5] = w * v1.y; acc[6] = w * v1.z; acc[7] = w * v1.w;
    }
    int p0 = g_rowptr[dst], p1 = g_rowptr[dst + 1];
    for (int p = p0; p < p1; p++) {
        int s = g_col[p];
        float w = g_w[p];
        const float4* r = (const float4*)(rowbase + (size_t)s * CC);
        float4 v0 = r[lane], v1 = r[lane + 32];
        acc[0] = fmaf(w, v0.x, acc[0]); acc[1] = fmaf(w, v0.y, acc[1]);
        acc[2] = fmaf(w, v0.z, acc[2]); acc[3] = fmaf(w, v0.w, acc[3]);
        acc[4] = fmaf(w, v1.x, acc[4]); acc[5] = fmaf(w, v1.y, acc[5]);
        acc[6] = fmaf(w, v1.z, acc[6]); acc[7] = fmaf(w, v1.w, acc[7]);
    }
    float4 b0 = ((const float4*)bias)[lane], b1 = ((const float4*)bias)[lane + 32];
    acc[0] += b0.x; acc[1] += b0.y; acc[2] += b0.z; acc[3] += b0.w;
    acc[4] += b1.x; acc[5] += b1.y; acc[6] += b1.z; acc[7] += b1.w;
    float4* o = (float4*)(agg + ((size_t)g * LL + dst) * CC);
    o[lane]      = make_float4(acc[0], acc[1], acc[2], acc[3]);
    o[lane + 32] = make_float4(acc[4], acc[5], acc[6], acc[7]);
}

// ---------------- BN stats (two-stage deterministic) ----------------
__global__ void k_bnpart(const float* __restrict__ a, float* __restrict__ part, int M) {
    int c = threadIdx.x;             // channel
    int rpb = M / PARTS;
    int r0 = blockIdx.x * rpb;
    float s = 0.f, q = 0.f;
    for (int r = 0; r < rpb; r++) {
        float v = a[(size_t)(r0 + r) * CC + c];
        s += v;
        q = fmaf(v, v, q);
    }
    part[blockIdx.x * (2*CC) + c]      = s;
    part[blockIdx.x * (2*CC) + CC + c] = q;
}

__global__ void k_bnfinal(const float* __restrict__ part,
                          const float* __restrict__ gamma, const float* __restrict__ beta,
                          float* __restrict__ scale, float* __restrict__ shift, int M) {
    int c = threadIdx.x;
    float s = 0.f, q = 0.f;
    for (int p = 0; p < PARTS; p++) {
        s += part[p * (2*CC) + c];
        q += part[p * (2*CC) + CC + c];
    }
    float invM = 1.0f / (float)M;
    float mean = s * invM;
    float var  = q * invM - mean * mean;
    float sc = gamma[c] * rsqrtf(var + 1e-5f);
    scale[c] = sc;
    shift[c] = beta[c] - mean * sc;
}

// ---------------- fused BN-apply + branch add + ReLU ----------------
__global__ void k_finalize(float* __restrict__ outp) {
    size_t i4 = (size_t)blockIdx.x * blockDim.x + threadIdx.x;  // over GG*LL*64 float4s
    float4 a = ((const float4*)g_bufAG)[i4];
    size_t c4 = i4 & 63;
    size_t row = i4 >> 6;
    size_t l = row % LL;
    size_t g = row / LL;
    size_t b = g >> 3;
    float4 as = ((const float4*)g_aggs)[((b * LL + l) << 6) + c4];
    float4 s1 = ((const float4*)g_scale1)[c4], h1 = ((const float4*)g_shift1)[c4];
    float4 s2 = ((const float4*)g_scale2)[c4], h2 = ((const float4*)g_shift2)[c4];
    float4 o;
    o.x = fmaxf(fmaf(a.x, s1.x, h1.x) + fmaf(as.x, s2.x, h2.x), 0.f);
    o.y = fmaxf(fmaf(a.y, s1.y, h1.y) + fmaf(as.y, s2.y, h2.y), 0.f);
    o.z = fmaxf(fmaf(a.z, s1.z, h1.z) + fmaf(as.z, s2.z, h2.z), 0.f);
    o.w = fmaxf(fmaf(a.w, s1.w, h1.w) + fmaf(as.w, s2.w, h2.w), 0.f);
    ((float4*)outp)[i4] = o;
}

// ---------------- launch ----------------
extern "C" void kernel_launch(void* const* d_in, const int* in_sizes, int n_in,
                              void* d_out, int out_size) {
    const float* x  = (const float*)d_in[0];
    const int*   ei = (const int*)  d_in[1];
    const float* W [3] = {(const float*)d_in[2],  (const float*)d_in[4],  (const float*)d_in[6]};
    const float* bv[3] = {(const float*)d_in[3],  (const float*)d_in[5],  (const float*)d_in[7]};
    const float* Ws[3] = {(const float*)d_in[8],  (const float*)d_in[10], (const float*)d_in[12]};
    const float* bs[3] = {(const float*)d_in[9],  (const float*)d_in[11], (const float*)d_in[13]};
    const float* ga[3] = {(const float*)d_in[14], (const float*)d_in[16], (const float*)d_in[18]};
    const float* be[3] = {(const float*)d_in[15], (const float*)d_in[17], (const float*)d_in[19]};
    const float* gs[3] = {(const float*)d_in[20], (const float*)d_in[22], (const float*)d_in[24]};
    const float* bes[3]= {(const float*)d_in[21], (const float*)d_in[23], (const float*)d_in[25]};

    float *bufX, *bufHW, *bufAG, *xp, *hws, *aggs, *part, *parts, *sc1, *sh1, *sc2, *sh2;
    cudaGetSymbolAddress((void**)&bufX,  g_bufX);
    cudaGetSymbolAddress((void**)&bufHW, g_bufHW);
    cudaGetSymbolAddress((void**)&bufAG, g_bufAG);
    cudaGetSymbolAddress((void**)&xp,    g_xp);
    cudaGetSymbolAddress((void**)&hws,   g_hws);
    cudaGetSymbolAddress((void**)&aggs,  g_aggs);
    cudaGetSymbolAddress((void**)&part,  g_part);
    cudaGetSymbolAddress((void**)&parts, g_parts);
    cudaGetSymbolAddress((void**)&sc1,   g_scale1);
    cudaGetSymbolAddress((void**)&sh1,   g_shift1);
    cudaGetSymbolAddress((void**)&sc2,   g_scale2);
    cudaGetSymbolAddress((void**)&sh2,   g_shift2);

    // graph preprocessing (deterministic)
    k_zero_graph<<<(LL + 255) / 256, 256>>>();
    k_deg<<<EE / 256, 256>>>(ei);
    k_dis<<<(LL + 255) / 256, 256>>>();
    k_scan<<<1, 1024>>>();
    k_fill<<<LL / 8, 256>>>(ei);

    k_transpose_in<<<dim3(LL / 32, C0 / 32, GG), dim3(32, 8)>>>(x);

    int Cin = C0;
    for (int layer = 0; layer < 3; layer++) {
        k_pool<<<(BB * LL * Cin + 255) / 256, 256>>>(Cin);
        k_gemm<<<dim3(CC / 128, GG * LL / 128), 256>>>(bufX, W[layer], bufHW, GG * LL, Cin);
        k_gemm<<<dim3(CC / 128, BB * LL / 128), 256>>>(xp, Ws[layer], hws, BB * LL, Cin);
        k_spmm<<<GG * LL / 8, 256>>>(bufHW, bufAG, bv[layer], GG);
        k_spmm<<<BB * LL / 8, 256>>>(hws, aggs, bs[layer], BB);
        k_bnpart<<<PARTS, 256>>>(bufAG, part, GG * LL);
        k_bnpart<<<PARTS, 256>>>(aggs, parts, BB * LL);
        k_bnfinal<<<1, 256>>>(part,  ga[layer], be[layer],  sc1, sh1, GG * LL);
        k_bnfinal<<<1, 256>>>(parts, gs[layer], bes[layer], sc2, sh2, BB * LL);
        k_finalize<<<(GG * LL * (CC / 4)) / 256, 256>>>(bufX);
        Cin = CC;
    }
    k_transpose_out<<<dim3(LL / 32, CC / 32, GG), dim3(32, 8)>>>((float*)d_out);
}

// round 3
// speedup vs baseline: 1.2909x; 1.2909x over previous
#include <cuda_runtime.h>
#include <cuda_bf16.h>
#include <cstdint>
#include <cfloat>

// Problem constants
#define BB 4
#define NN 8
#define GG 32          // BB*NN
#define LL 2048
#define EE 16384
#define C0 128
#define CC 256
#define PARTS 256
#define PAD 40         // padded SMEM row length in bf16 elems (80 bytes)

// ---------------- scratch (device globals; no allocation allowed) ----------------
__device__ __align__(16) float g_bufX [(size_t)GG*LL*CC];   // activations, LC layout [g][l][c]
__device__ __align__(16) float g_bufHW[(size_t)GG*LL*CC];   // gemm output  [g][l][co]
__device__ __align__(16) float g_bufAG[(size_t)GG*LL*CC];   // aggregated   [g][l][co]
__device__ __align__(16) float g_xp   [(size_t)BB*LL*CC];   // pooled       [b][l][c]
__device__ __align__(16) float g_hws  [(size_t)BB*LL*CC];
__device__ __align__(16) float g_aggs [(size_t)BB*LL*CC];

__device__ float g_deg[LL];
__device__ float g_dis[LL];
__device__ float g_selfw[LL];
__device__ int   g_cnt[LL];
__device__ int   g_rowptr[LL+1];
__device__ int   g_col[EE];
__device__ float g_w[EE];

__device__ __align__(16) float g_part [PARTS*2*CC];
__device__ __align__(16) float g_parts[PARTS*2*CC];
__device__ __align__(16) float g_scale1[CC], g_shift1[CC], g_scale2[CC], g_shift2[CC];

// bf16-split, transposed weights: [N=256][K] row-major
__device__ __align__(16) __nv_bfloat16 g_wt_hi [CC*CC];
__device__ __align__(16) __nv_bfloat16 g_wt_lo [CC*CC];
__device__ __align__(16) __nv_bfloat16 g_wts_hi[CC*CC];
__device__ __align__(16) __nv_bfloat16 g_wts_lo[CC*CC];

// ---------------- helpers ----------------
__device__ __forceinline__ uint32_t smem_u32(const void* p) {
    uint32_t a;
    asm("{ .reg .u64 t; cvta.to.shared.u64 t, %1; cvt.u32.u64 %0, t; }" : "=r"(a) : "l"(p));
    return a;
}
__device__ __forceinline__ void ldx4(uint32_t* r, uint32_t addr) {
    asm volatile("ldmatrix.sync.aligned.m8n8.x4.shared.b16 {%0,%1,%2,%3}, [%4];"
        : "=r"(r[0]), "=r"(r[1]), "=r"(r[2]), "=r"(r[3]) : "r"(addr));
}
__device__ __forceinline__ void mma_bf16(float* c, const uint32_t* a, const uint32_t* b) {
    asm volatile(
        "mma.sync.aligned.m16n8k16.row.col.f32.bf16.bf16.f32 "
        "{%0,%1,%2,%3}, {%4,%5,%6,%7}, {%8,%9}, {%0,%1,%2,%3};"
        : "+f"(c[0]), "+f"(c[1]), "+f"(c[2]), "+f"(c[3])
        : "r"(a[0]), "r"(a[1]), "r"(a[2]), "r"(a[3]), "r"(b[0]), "r"(b[1]));
}
__device__ __forceinline__ uint32_t bpack(__nv_bfloat16 a, __nv_bfloat16 b) {
    __nv_bfloat162 t;
    t.x = a; t.y = b;
    return *reinterpret_cast<uint32_t*>(&t);
}

// ---------------- graph preprocessing ----------------
__global__ void k_zero_graph() {
    int i = blockIdx.x*blockDim.x + threadIdx.x;
    if (i < LL) { g_deg[i] = 0.f; g_cnt[i] = 0; }
}

__global__ void k_deg(const int* __restrict__ ei) {
    int e = blockIdx.x*blockDim.x + threadIdx.x;
    if (e < EE) {
        int dst = ei[EE + e];
        atomicAdd(&g_deg[dst], 1.0f);
        atomicAdd(&g_cnt[dst], 1);
    }
}

__global__ void k_dis() {
    int i = blockIdx.x*blockDim.x + threadIdx.x;
    if (i < LL) {
        float d = g_deg[i] + 2.0f;
        float r = rsqrtf(d);
        g_dis[i] = r;
        g_selfw[i] = 2.0f * r * r;
    }
}

__global__ void k_scan() {
    __shared__ int s[2][LL];
    int t = threadIdx.x;
    s[0][t]        = g_cnt[t];
    s[0][t + 1024] = g_cnt[t + 1024];
    __syncthreads();
    int cur = 0;
    for (int off = 1; off < LL; off <<= 1) {
        int nxt = cur ^ 1;
        for (int i = t; i < LL; i += 1024) {
            int v = s[cur][i];
            if (i >= off) v += s[cur][i - off];
            s[nxt][i] = v;
        }
        __syncthreads();
        cur = nxt;
    }
    for (int i = t; i < LL; i += 1024) g_rowptr[i + 1] = s[cur][i];
    if (t == 0) g_rowptr[0] = 0;
}

__global__ void k_fill(const int* __restrict__ ei) {
    int wid  = (blockIdx.x*blockDim.x + threadIdx.x) >> 5;
    int lane = threadIdx.x & 31;
    if (wid >= LL) return;
    int node = wid;
    int base = g_rowptr[node];
    float dn = g_dis[node];
    int count = 0;
    for (int e0 = 0; e0 < EE; e0 += 32) {
        int e = e0 + lane;
        int d = ei[EE + e];
        bool m = (d == node);
        unsigned mask = __ballot_sync(0xffffffffu, m);
        if (m) {
            int rank = __popc(mask & ((1u << lane) - 1u));
            int s = ei[e];
            g_col[base + count + rank] = s;
            g_w  [base + count + rank] = g_dis[s] * dn;
        }
        count += __popc(mask);
    }
}

// ---------------- layout transforms ----------------
__global__ void k_transpose_in(const float* __restrict__ x) {
    __shared__ float tile[32][33];
    int g = blockIdx.z;
    int l0 = blockIdx.x * 32, c0 = blockIdx.y * 32;
    int tx = threadIdx.x, ty = threadIdx.y;
    const float* src = x + (size_t)g * C0 * LL;
    #pragma unroll
    for (int i = ty; i < 32; i += 8)
        tile[i][tx] = src[(size_t)(c0 + i) * LL + l0 + tx];
    __syncthreads();
    float* dstp = g_bufX + (size_t)g * LL * C0;
    #pragma unroll
    for (int i = ty; i < 32; i += 8)
        dstp[(size_t)(l0 + i) * C0 + c0 + tx] = tile[tx][i];
}

__global__ void k_transpose_out(float* __restrict__ out) {
    __shared__ float tile[32][33];
    int g = blockIdx.z;
    int l0 = blockIdx.x * 32, c0 = blockIdx.y * 32;
    int tx = threadIdx.x, ty = threadIdx.y;
    #pragma unroll
    for (int i = ty; i < 32; i += 8)
        tile[i][tx] = g_bufX[((size_t)g * LL + l0 + i) * CC + c0 + tx];
    __syncthreads();
    #pragma unroll
    for (int i = ty; i < 32; i += 8)
        out[((size_t)g * CC + c0 + i) * LL + l0 + tx] = tile[tx][i];
}

__global__ void k_pool(int Cin) {
    int idx = blockIdx.x*blockDim.x + threadIdx.x;
    int tot = BB * LL * Cin;
    if (idx >= tot) return;
    int per = LL * Cin;
    int b = idx / per;
    int rem = idx - b * per;
    const float* base = g_bufX + (size_t)b * NN * per;
    float m = -FLT_MAX;
    #pragma unroll
    for (int n = 0; n < NN; n++)
        m = fmaxf(m, base[(size_t)n * per + rem]);
    g_xp[idx] = m;
}

// ---------------- weight transpose + bf16 split ----------------
__global__ void k_wsplit(const float* __restrict__ W,
                         __nv_bfloat16* __restrict__ wt_hi,
                         __nv_bfloat16* __restrict__ wt_lo, int K) {
    int idx = blockIdx.x*blockDim.x + threadIdx.x;   // over K*256, k-major
    if (idx >= K * CC) return;
    int k = idx >> 8, n = idx & 255;
    float v = W[idx];  // W[k][n]
    __nv_bfloat16 h = __float2bfloat16(v);
    float lo = v - __bfloat162float(h);
    wt_hi[(size_t)n * K + k] = h;
    wt_lo[(size_t)n * K + k] = __float2bfloat16(lo);
}

// ---------------- HMMA split-bf16 GEMM: C[M,256] = A[M,K] * Wt^T ----------------
// A fp32 row-major [M,K]; Wt hi/lo bf16 [256][K] row-major.
// grid (2, M/128), 256 threads. CTA tile 128x128, warp tile 32x64, K-chunk 32.
__global__ __launch_bounds__(256, 1)
void k_gemm_mma(const float* __restrict__ A,
                const __nv_bfloat16* __restrict__ Bhg,
                const __nv_bfloat16* __restrict__ Blg,
                float* __restrict__ Cc, int K) {
    __shared__ __nv_bfloat16 sAh[128 * PAD];
    __shared__ __nv_bfloat16 sAl[128 * PAD];
    __shared__ __nv_bfloat16 sBh[128 * PAD];
    __shared__ __nv_bfloat16 sBl[128 * PAD];

    int tid  = threadIdx.x;
    int lane = tid & 31;
    int warp = tid >> 5;
    int wm = warp & 3;           // m 32-block
    int wn = warp >> 2;          // n 64-block
    int n0c = blockIdx.x * 128;
    int m0  = blockIdx.y * 128;

    uint32_t sAh_b = smem_u32(sAh), sAl_b = smem_u32(sAl);
    uint32_t sBh_b = smem_u32(sBh), sBl_b = smem_u32(sBl);

    float acc[2][8][4];
    #pragma unroll
    for (int i = 0; i < 2; i++)
        #pragma unroll
        for (int j = 0; j < 8; j++)
            #pragma unroll
            for (int t = 0; t < 4; t++) acc[i][j][t] = 0.f;

    int lr = tid >> 1;            // staging row 0..127
    int lh = (tid & 1) << 4;      // k offset 0 / 16

    int nchunks = K >> 5;
    for (int kc = 0; kc < nchunks; kc++) {
        // ---- stage A [128 x 32] fp32 -> hi/lo bf16 ----
        {
            const float* ap = A + (size_t)(m0 + lr) * K + kc * 32 + lh;
            uint32_t so = (uint32_t)(lr * PAD + lh) * 2;   // byte offset
            #pragma unroll
            for (int j = 0; j < 16; j += 8) {
                float4 u = *(const float4*)(ap + j);
                float4 v = *(const float4*)(ap + j + 4);
                float f[8] = {u.x, u.y, u.z, u.w, v.x, v.y, v.z, v.w};
                __nv_bfloat16 h[8], l[8];
                #pragma unroll
                for (int t = 0; t < 8; t++) {
                    h[t] = __float2bfloat16(f[t]);
                    l[t] = __float2bfloat16(f[t] - __bfloat162float(h[t]));
                }
                uint4 ph = make_uint4(bpack(h[0],h[1]), bpack(h[2],h[3]),
                                      bpack(h[4],h[5]), bpack(h[6],h[7]));
                uint4 pl = make_uint4(bpack(l[0],l[1]), bpack(l[2],l[3]),
                                      bpack(l[4],l[5]), bpack(l[6],l[7]));
                *(uint4*)((char*)sAh + so + j * 2) = ph;
                *(uint4*)((char*)sAl + so + j * 2) = pl;
            }
        }
        // ---- stage B [128 x 32] bf16 hi/lo ----
        {
            const __nv_bfloat16* bh = Bhg + (size_t)(n0c + lr) * K + kc * 32 + lh;
            const __nv_bfloat16* bl = Blg + (size_t)(n0c + lr) * K + kc * 32 + lh;
            uint32_t so = (uint32_t)(lr * PAD + lh) * 2;
            *(uint4*)((char*)sBh + so)      = *(const uint4*)(bh);
            *(uint4*)((char*)sBh + so + 16) = *(const uint4*)(bh + 8);
            *(uint4*)((char*)sBl + so)      = *(const uint4*)(bl);
            *(uint4*)((char*)sBl + so + 16) = *(const uint4*)(bl + 8);
        }
        __syncthreads();

        #pragma unroll
        for (int ks = 0; ks < 2; ks++) {
            // A fragments: row = wm*32 + (lane&15) [+16], col = ks*16 + (lane>>4)*8
            uint32_t a_hi[2][4], a_lo[2][4];
            {
                int row = wm * 32 + (lane & 15);
                int col = ks * 16 + (lane >> 4) * 8;
                #pragma unroll
                for (int mt = 0; mt < 2; mt++) {
                    uint32_t off = (uint32_t)((row + mt * 16) * PAD + col) * 2;
                    ldx4(a_hi[mt], sAh_b + off);
                    ldx4(a_lo[mt], sAl_b + off);
                }
            }
            // B fragments: row = wn*64 + (lane&7) + ((lane>>4)<<3) [+16*i],
            //              col = ks*16 + ((lane>>3)&1)*8
            uint32_t b_hi[8][2], b_lo[8][2];
            {
                int row = wn * 64 + (lane & 7) + ((lane >> 4) << 3);
                int col = ks * 16 + ((lane >> 3) & 1) * 8;
                #pragma unroll
                for (int i = 0; i < 4; i++) {
                    uint32_t off = (uint32_t)((row + i * 16) * PAD + col) * 2;
                    uint32_t r[4];
                    ldx4(r, sBh_b + off);
                    b_hi[i*2][0] = r[0]; b_hi[i*2][1] = r[1];
                    b_hi[i*2+1][0] = r[2]; b_hi[i*2+1][1] = r[3];
                    ldx4(r, sBl_b + off);
                    b_lo[i*2][0] = r[0]; b_lo[i*2][1] = r[1];
                    b_lo[i*2+1][0] = r[2]; b_lo[i*2+1][1] = r[3];
                }
            }
            #pragma unroll
            for (int mt = 0; mt < 2; mt++)
                #pragma unroll
                for (int nt = 0; nt < 8; nt++) {
                    mma_bf16(acc[mt][nt], a_hi[mt], b_hi[nt]);   // Ah*Bh
                    mma_bf16(acc[mt][nt], a_hi[mt], b_lo[nt]);   // Ah*Bl
                    mma_bf16(acc[mt][nt], a_lo[mt], b_hi[nt]);   // Al*Bh
                }
        }
        __syncthreads();
    }

    // ---- epilogue ----
    int crow = m0 + wm * 32 + (lane >> 2);
    int ccol = n0c + wn * 64 + (lane & 3) * 2;
    #pragma unroll
    for (int mt = 0; mt < 2; mt++) {
        #pragma unroll
        for (int nt = 0; nt < 8; nt++) {
            float* cp = Cc + (size_t)(crow + mt * 16) * CC + ccol + nt * 8;
            *(float2*)cp              = make_float2(acc[mt][nt][0], acc[mt][nt][1]);
            *(float2*)(cp + 8 * CC)   = make_float2(acc[mt][nt][2], acc[mt][nt][3]);
        }
    }
}

// ---------------- SpMM ----------------
__global__ void k_spmm(const float* __restrict__ hw, float* __restrict__ agg,
                       const float* __restrict__ bias, int Gc) {
    int wid  = (blockIdx.x*blockDim.x + threadIdx.x) >> 5;
    int lane = threadIdx.x & 31;
    if (wid >= Gc * LL) return;
    int g = wid / LL, dst = wid - g * LL;
    const float* rowbase = hw + (size_t)g * LL * CC;
    float acc[8];
    {
        float w = g_selfw[dst];
        const float4* r = (const float4*)(rowbase + (size_t)dst * CC);
        float4 v0 = r[lane], v1 = r[lane + 32];
        acc[0] = w * v0.x; acc[1] = w * v0.y; acc[2] = w * v0.z; acc[3] = w * v0.w;
        acc[4] = w * v1.x; acc[5] = w * v1.y; acc[6] = w * v1.z; acc[7] = w * v1.w;
    }
    int p0 = g_rowptr[dst], p1 = g_rowptr[dst + 1];
    for (int p = p0; p < p1; p++) {
        int s = g_col[p];
        float w = g_w[p];
        const float4* r = (const float4*)(rowbase + (size_t)s * CC);
        float4 v0 = r[lane], v1 = r[lane + 32];
        acc[0] = fmaf(w, v0.x, acc[0]); acc[1] = fmaf(w, v0.y, acc[1]);
        acc[2] = fmaf(w, v0.z, acc[2]); acc[3] = fmaf(w, v0.w, acc[3]);
        acc[4] = fmaf(w, v1.x, acc[4]); acc[5] = fmaf(w, v1.y, acc[5]);
        acc[6] = fmaf(w, v1.z, acc[6]); acc[7] = fmaf(w, v1.w, acc[7]);
    }
    float4 b0 = ((const float4*)bias)[lane], b1 = ((const float4*)bias)[lane + 32];
    acc[0] += b0.x; acc[1] += b0.y; acc[2] += b0.z; acc[3] += b0.w;
    acc[4] += b1.x; acc[5] += b1.y; acc[6] += b1.z; acc[7] += b1.w;
    float4* o = (float4*)(agg + ((size_t)g * LL + dst) * CC);
    o[lane]      = make_float4(acc[0], acc[1], acc[2], acc[3]);
    o[lane + 32] = make_float4(acc[4], acc[5], acc[6], acc[7]);
}

// ---------------- BN stats (two-stage deterministic) ----------------
__global__ void k_bnpart(const float* __restrict__ a, float* __restrict__ part, int M) {
    int c = threadIdx.x;
    int rpb = M / PARTS;
    int r0 = blockIdx.x * rpb;
    float s = 0.f, q = 0.f;
    for (int r = 0; r < rpb; r++) {
        float v = a[(size_t)(r0 + r) * CC + c];
        s += v;
        q = fmaf(v, v, q);
    }
    part[blockIdx.x * (2*CC) + c]      = s;
    part[blockIdx.x * (2*CC) + CC + c] = q;
}

__global__ void k_bnfinal(const float* __restrict__ part,
                          const float* __restrict__ gamma, const float* __restrict__ beta,
                          float* __restrict__ scale, float* __restrict__ shift, int M) {
    int c = threadIdx.x;
    float s = 0.f, q = 0.f;
    for (int p = 0; p < PARTS; p++) {
        s += part[p * (2*CC) + c];
        q += part[p * (2*CC) + CC + c];
    }
    float invM = 1.0f / (float)M;
    float mean = s * invM;
    float var  = q * invM - mean * mean;
    float sc = gamma[c] * rsqrtf(var + 1e-5f);
    scale[c] = sc;
    shift[c] = beta[c] - mean * sc;
}

// ---------------- fused BN-apply + branch add + ReLU ----------------
__global__ void k_finalize(float* __restrict__ outp) {
    size_t i4 = (size_t)blockIdx.x * blockDim.x + threadIdx.x;
    float4 a = ((const float4*)g_bufAG)[i4];
    size_t c4 = i4 & 63;
    size_t row = i4 >> 6;
    size_t l = row % LL;
    size_t g = row / LL;
    size_t b = g >> 3;
    float4 as = ((const float4*)g_aggs)[((b * LL + l) << 6) + c4];
    float4 s1 = ((const float4*)g_scale1)[c4], h1 = ((const float4*)g_shift1)[c4];
    float4 s2 = ((const float4*)g_scale2)[c4], h2 = ((const float4*)g_shift2)[c4];
    float4 o;
    o.x = fmaxf(fmaf(a.x, s1.x, h1.x) + fmaf(as.x, s2.x, h2.x), 0.f);
    o.y = fmaxf(fmaf(a.y, s1.y, h1.y) + fmaf(as.y, s2.y, h2.y), 0.f);
    o.z = fmaxf(fmaf(a.z, s1.z, h1.z) + fmaf(as.z, s2.z, h2.z), 0.f);
    o.w = fmaxf(fmaf(a.w, s1.w, h1.w) + fmaf(as.w, s2.w, h2.w), 0.f);
    ((float4*)outp)[i4] = o;
}

// ---------------- launch ----------------
extern "C" void kernel_launch(void* const* d_in, const int* in_sizes, int n_in,
                              void* d_out, int out_size) {
    const float* x  = (const float*)d_in[0];
    const int*   ei = (const int*)  d_in[1];
    const float* W [3] = {(const float*)d_in[2],  (const float*)d_in[4],  (const float*)d_in[6]};
    const float* bv[3] = {(const float*)d_in[3],  (const float*)d_in[5],  (const float*)d_in[7]};
    const float* Ws[3] = {(const float*)d_in[8],  (const float*)d_in[10], (const float*)d_in[12]};
    const float* bs[3] = {(const float*)d_in[9],  (const float*)d_in[11], (const float*)d_in[13]};
    const float* ga[3] = {(const float*)d_in[14], (const float*)d_in[16], (const float*)d_in[18]};
    const float* be[3] = {(const float*)d_in[15], (const float*)d_in[17], (const float*)d_in[19]};
    const float* gs[3] = {(const float*)d_in[20], (const float*)d_in[22], (const float*)d_in[24]};
    const float* bes[3]= {(const float*)d_in[21], (const float*)d_in[23], (const float*)d_in[25]};

    float *bufX, *bufHW, *bufAG, *xp, *hws, *aggs, *part, *parts, *sc1, *sh1, *sc2, *sh2;
    __nv_bfloat16 *wt_hi, *wt_lo, *wts_hi, *wts_lo;
    cudaGetSymbolAddress((void**)&bufX,  g_bufX);
    cudaGetSymbolAddress((void**)&bufHW, g_bufHW);
    cudaGetSymbolAddress((void**)&bufAG, g_bufAG);
    cudaGetSymbolAddress((void**)&xp,    g_xp);
    cudaGetSymbolAddress((void**)&hws,   g_hws);
    cudaGetSymbolAddress((void**)&aggs,  g_aggs);
    cudaGetSymbolAddress((void**)&part,  g_part);
    cudaGetSymbolAddress((void**)&parts, g_parts);
    cudaGetSymbolAddress((void**)&sc1,   g_scale1);
    cudaGetSymbolAddress((void**)&sh1,   g_shift1);
    cudaGetSymbolAddress((void**)&sc2,   g_scale2);
    cudaGetSymbolAddress((void**)&sh2,   g_shift2);
    cudaGetSymbolAddress((void**)&wt_hi,  g_wt_hi);
    cudaGetSymbolAddress((void**)&wt_lo,  g_wt_lo);
    cudaGetSymbolAddress((void**)&wts_hi, g_wts_hi);
    cudaGetSymbolAddress((void**)&wts_lo, g_wts_lo);

    // graph preprocessing (deterministic)
    k_zero_graph<<<(LL + 255) / 256, 256>>>();
    k_deg<<<EE / 256, 256>>>(ei);
    k_dis<<<(LL + 255) / 256, 256>>>();
    k_scan<<<1, 1024>>>();
    k_fill<<<LL / 8, 256>>>(ei);

    k_transpose_in<<<dim3(LL / 32, C0 / 32, GG), dim3(32, 8)>>>(x);

    int Cin = C0;
    for (int layer = 0; layer < 3; layer++) {
        k_wsplit<<<(Cin * CC + 255) / 256, 256>>>(W[layer],  wt_hi,  wt_lo,  Cin);
        k_wsplit<<<(Cin * CC + 255) / 256, 256>>>(Ws[layer], wts_hi, wts_lo, Cin);
        k_pool<<<(BB * LL * Cin + 255) / 256, 256>>>(Cin);
        k_gemm_mma<<<dim3(2, GG * LL / 128), 256>>>(bufX, wt_hi, wt_lo, bufHW, Cin);
        k_gemm_mma<<<dim3(2, BB * LL / 128), 256>>>(xp, wts_hi, wts_lo, hws, Cin);
        k_spmm<<<GG * LL / 8, 256>>>(bufHW, bufAG, bv[layer], GG);
        k_spmm<<<BB * LL / 8, 256>>>(hws, aggs, bs[layer], BB);
        k_bnpart<<<PARTS, 256>>>(bufAG, part, GG * LL);
        k_bnpart<<<PARTS, 256>>>(aggs, parts, BB * LL);
        k_bnfinal<<<1, 256>>>(part,  ga[layer], be[layer],  sc1, sh1, GG * LL);
        k_bnfinal<<<1, 256>>>(parts, gs[layer], bes[layer], sc2, sh2, BB * LL);
        k_finalize<<<(GG * LL * (CC / 4)) / 256, 256>>>(bufX);
        Cin = CC;
    }
    k_transpose_out<<<dim3(LL / 32, CC / 32, GG), dim3(32, 8)>>>((float*)d_out);
}

// round 4
// speedup vs baseline: 1.5522x; 1.2024x over previous
#include <cuda_runtime.h>
#include <cuda_bf16.h>
#include <cstdint>
#include <cfloat>

// Problem constants
#define BB 4
#define NN 8
#define GG 32          // BB*NN
#define LL 2048
#define EE 16384
#define C0 128
#define CC 256
#define PARTS 256
#define PAD 40         // padded SMEM row length in bf16 elems (80 bytes)

// ---------------- scratch (device globals; no allocation allowed) ----------------
__device__ __align__(16) float g_bufX [(size_t)GG*LL*CC];   // activations, LC layout [g][l][c]
__device__ __align__(16) float g_bufHW[(size_t)GG*LL*CC];   // gemm output  [g][l][co]
__device__ __align__(16) float g_bufAG[(size_t)GG*LL*CC];   // aggregated   [g][l][co]
__device__ __align__(16) float g_xp   [(size_t)BB*LL*CC];   // pooled       [b][l][c]
__device__ __align__(16) float g_hws  [(size_t)BB*LL*CC];
__device__ __align__(16) float g_aggs [(size_t)BB*LL*CC];

__device__ float g_deg[LL];
__device__ float g_dis[LL];
__device__ float g_selfw[LL];
__device__ int   g_cnt[LL];
__device__ int   g_rowptr[LL+1];
__device__ int   g_col[EE];
__device__ float g_w[EE];

__device__ __align__(16) float g_part [PARTS*2*CC];
__device__ __align__(16) float g_parts[PARTS*2*CC];
__device__ __align__(16) float g_scale1[CC], g_shift1[CC], g_scale2[CC], g_shift2[CC];

// bf16-split, transposed weights: [N=256][K] row-major
__device__ __align__(16) __nv_bfloat16 g_wt_hi [CC*CC];
__device__ __align__(16) __nv_bfloat16 g_wt_lo [CC*CC];
__device__ __align__(16) __nv_bfloat16 g_wts_hi[CC*CC];
__device__ __align__(16) __nv_bfloat16 g_wts_lo[CC*CC];

// ---------------- helpers ----------------
__device__ __forceinline__ uint32_t smem_u32(const void* p) {
    uint32_t a;
    asm("{ .reg .u64 t; cvta.to.shared.u64 t, %1; cvt.u32.u64 %0, t; }" : "=r"(a) : "l"(p));
    return a;
}
__device__ __forceinline__ void ldx4(uint32_t* r, uint32_t addr) {
    asm volatile("ldmatrix.sync.aligned.m8n8.x4.shared.b16 {%0,%1,%2,%3}, [%4];"
        : "=r"(r[0]), "=r"(r[1]), "=r"(r[2]), "=r"(r[3]) : "r"(addr));
}
__device__ __forceinline__ void mma_bf16(float* c, const uint32_t* a, const uint32_t* b) {
    asm volatile(
        "mma.sync.aligned.m16n8k16.row.col.f32.bf16.bf16.f32 "
        "{%0,%1,%2,%3}, {%4,%5,%6,%7}, {%8,%9}, {%0,%1,%2,%3};"
        : "+f"(c[0]), "+f"(c[1]), "+f"(c[2]), "+f"(c[3])
        : "r"(a[0]), "r"(a[1]), "r"(a[2]), "r"(a[3]), "r"(b[0]), "r"(b[1]));
}
__device__ __forceinline__ uint32_t bpack(__nv_bfloat16 a, __nv_bfloat16 b) {
    __nv_bfloat162 t;
    t.x = a; t.y = b;
    return *reinterpret_cast<uint32_t*>(&t);
}

// ---------------- graph preprocessing ----------------
__global__ void k_zero_graph() {
    int i = blockIdx.x*blockDim.x + threadIdx.x;
    if (i < LL) { g_deg[i] = 0.f; g_cnt[i] = 0; }
}

__global__ void k_deg(const int* __restrict__ ei) {
    int e = blockIdx.x*blockDim.x + threadIdx.x;
    if (e < EE) {
        int dst = ei[EE + e];
        atomicAdd(&g_deg[dst], 1.0f);
        atomicAdd(&g_cnt[dst], 1);
    }
}

__global__ void k_dis() {
    int i = blockIdx.x*blockDim.x + threadIdx.x;
    if (i < LL) {
        float d = g_deg[i] + 2.0f;
        float r = rsqrtf(d);
        g_dis[i] = r;
        g_selfw[i] = 2.0f * r * r;
    }
}

__global__ void k_scan() {
    __shared__ int s[2][LL];
    int t = threadIdx.x;
    s[0][t]        = g_cnt[t];
    s[0][t + 1024] = g_cnt[t + 1024];
    __syncthreads();
    int cur = 0;
    for (int off = 1; off < LL; off <<= 1) {
        int nxt = cur ^ 1;
        for (int i = t; i < LL; i += 1024) {
            int v = s[cur][i];
            if (i >= off) v += s[cur][i - off];
            s[nxt][i] = v;
        }
        __syncthreads();
        cur = nxt;
    }
    for (int i = t; i < LL; i += 1024) g_rowptr[i + 1] = s[cur][i];
    if (t == 0) g_rowptr[0] = 0;
}

__global__ void k_fill(const int* __restrict__ ei) {
    int wid  = (blockIdx.x*blockDim.x + threadIdx.x) >> 5;
    int lane = threadIdx.x & 31;
    if (wid >= LL) return;
    int node = wid;
    int base = g_rowptr[node];
    float dn = g_dis[node];
    int count = 0;
    for (int e0 = 0; e0 < EE; e0 += 32) {
        int e = e0 + lane;
        int d = ei[EE + e];
        bool m = (d == node);
        unsigned mask = __ballot_sync(0xffffffffu, m);
        if (m) {
            int rank = __popc(mask & ((1u << lane) - 1u));
            int s = ei[e];
            g_col[base + count + rank] = s;
            g_w  [base + count + rank] = g_dis[s] * dn;
        }
        count += __popc(mask);
    }
}

// ---------------- layout transforms ----------------
__global__ void k_transpose_in(const float* __restrict__ x) {
    __shared__ float tile[32][33];
    int g = blockIdx.z;
    int l0 = blockIdx.x * 32, c0 = blockIdx.y * 32;
    int tx = threadIdx.x, ty = threadIdx.y;
    const float* src = x + (size_t)g * C0 * LL;
    #pragma unroll
    for (int i = ty; i < 32; i += 8)
        tile[i][tx] = src[(size_t)(c0 + i) * LL + l0 + tx];
    __syncthreads();
    float* dstp = g_bufX + (size_t)g * LL * C0;
    #pragma unroll
    for (int i = ty; i < 32; i += 8)
        dstp[(size_t)(l0 + i) * C0 + c0 + tx] = tile[tx][i];
}

__global__ void k_pool(int Cin) {
    int idx = blockIdx.x*blockDim.x + threadIdx.x;
    int tot = BB * LL * Cin;
    if (idx >= tot) return;
    int per = LL * Cin;
    int b = idx / per;
    int rem = idx - b * per;
    const float* base = g_bufX + (size_t)b * NN * per;
    float m = -FLT_MAX;
    #pragma unroll
    for (int n = 0; n < NN; n++)
        m = fmaxf(m, base[(size_t)n * per + rem]);
    g_xp[idx] = m;
}

// ---------------- weight transpose + bf16 split ----------------
__global__ void k_wsplit(const float* __restrict__ W,
                         __nv_bfloat16* __restrict__ wt_hi,
                         __nv_bfloat16* __restrict__ wt_lo, int K) {
    int idx = blockIdx.x*blockDim.x + threadIdx.x;   // over K*256, k-major
    if (idx >= K * CC) return;
    int k = idx >> 8, n = idx & 255;
    float v = W[idx];  // W[k][n]
    __nv_bfloat16 h = __float2bfloat16(v);
    float lo = v - __bfloat162float(h);
    wt_hi[(size_t)n * K + k] = h;
    wt_lo[(size_t)n * K + k] = __float2bfloat16(lo);
}

// ---------------- HMMA split-bf16 GEMM, double-buffered ----------------
// C[M,256] = A[M,K] * Wt^T. A fp32 row-major [M,K]; Wt hi/lo bf16 [256][K].
// grid (2, M/128), 256 threads. CTA tile 128x128, warp tile 32x64, K-chunk 32.
// Dynamic SMEM: 2 stages x {Ah,Al,Bh,Bl each 128*PAD*2 bytes}.
#define OFF_AH 0
#define OFF_AL 10240
#define OFF_BH 20480
#define OFF_BL 30720
#define STAGE  40960

__global__ __launch_bounds__(256, 1)
void k_gemm_mma(const float* __restrict__ A,
                const __nv_bfloat16* __restrict__ Bhg,
                const __nv_bfloat16* __restrict__ Blg,
                float* __restrict__ Cc, int K) {
    extern __shared__ char sm[];
    int tid  = threadIdx.x;
    int lane = tid & 31;
    int warp = tid >> 5;
    int wm = warp & 3;           // m 32-block
    int wn = warp >> 2;          // n 64-block
    int n0c = blockIdx.x * 128;
    int m0  = blockIdx.y * 128;

    float acc[2][8][4];
    #pragma unroll
    for (int i = 0; i < 2; i++)
        #pragma unroll
        for (int j = 0; j < 8; j++)
            #pragma unroll
            for (int t = 0; t < 4; t++) acc[i][j][t] = 0.f;

    int lr = tid >> 1;            // staging row 0..127
    int lc = (tid & 1) << 4;      // col 0 / 16
    uint32_t so = (uint32_t)(lr * PAD + lc) * 2;   // byte offset within a matrix

    float aR[16];
    uint4 bhR0, bhR1, blR0, blR1;

    int nchunks = K >> 5;

#define GLOAD(kc) do { \
    const float* ap = A + (size_t)(m0 + lr) * K + (kc) * 32 + lc; \
    *(float4*)(aR)      = *(const float4*)(ap); \
    *(float4*)(aR + 4)  = *(const float4*)(ap + 4); \
    *(float4*)(aR + 8)  = *(const float4*)(ap + 8); \
    *(float4*)(aR + 12) = *(const float4*)(ap + 12); \
    const __nv_bfloat16* bhp = Bhg + (size_t)(n0c + lr) * K + (kc) * 32 + lc; \
    const __nv_bfloat16* blp = Blg + (size_t)(n0c + lr) * K + (kc) * 32 + lc; \
    bhR0 = *(const uint4*)(bhp); bhR1 = *(const uint4*)(bhp + 8); \
    blR0 = *(const uint4*)(blp); blR1 = *(const uint4*)(blp + 8); \
} while (0)

#define SSTORE(stg) do { \
    char* sb = sm + (stg) * STAGE; \
    __nv_bfloat16 h[16], l[16]; \
    _Pragma("unroll") \
    for (int t = 0; t < 16; t++) { \
        h[t] = __float2bfloat16(aR[t]); \
        l[t] = __float2bfloat16(aR[t] - __bfloat162float(h[t])); \
    } \
    *(uint4*)(sb + OFF_AH + so)      = make_uint4(bpack(h[0],h[1]),  bpack(h[2],h[3]), \
                                                  bpack(h[4],h[5]),  bpack(h[6],h[7])); \
    *(uint4*)(sb + OFF_AH + so + 16) = make_uint4(bpack(h[8],h[9]),  bpack(h[10],h[11]), \
                                                  bpack(h[12],h[13]),bpack(h[14],h[15])); \
    *(uint4*)(sb + OFF_AL + so)      = make_uint4(bpack(l[0],l[1]),  bpack(l[2],l[3]), \
                                                  bpack(l[4],l[5]),  bpack(l[6],l[7])); \
    *(uint4*)(sb + OFF_AL + so + 16) = make_uint4(bpack(l[8],l[9]),  bpack(l[10],l[11]), \
                                                  bpack(l[12],l[13]),bpack(l[14],l[15])); \
    *(uint4*)(sb + OFF_BH + so)      = bhR0; \
    *(uint4*)(sb + OFF_BH + so + 16) = bhR1; \
    *(uint4*)(sb + OFF_BL + so)      = blR0; \
    *(uint4*)(sb + OFF_BL + so + 16) = blR1; \
} while (0)

    // prologue
    GLOAD(0);
    SSTORE(0);
    __syncthreads();

    for (int kc = 0; kc < nchunks; kc++) {
        int cur = kc & 1;
        if (kc + 1 < nchunks) GLOAD(kc + 1);

        uint32_t sb = smem_u32(sm + cur * STAGE);
        #pragma unroll
        for (int ks = 0; ks < 2; ks++) {
            uint32_t a_hi[2][4], a_lo[2][4];
            {
                int row = wm * 32 + (lane & 15);
                int col = ks * 16 + (lane >> 4) * 8;
                #pragma unroll
                for (int mt = 0; mt < 2; mt++) {
                    uint32_t off = (uint32_t)((row + mt * 16) * PAD + col) * 2;
                    ldx4(a_hi[mt], sb + OFF_AH + off);
                    ldx4(a_lo[mt], sb + OFF_AL + off);
                }
            }
            uint32_t b_hi[8][2], b_lo[8][2];
            {
                int row = wn * 64 + (lane & 7) + ((lane >> 4) << 3);
                int col = ks * 16 + ((lane >> 3) & 1) * 8;
                #pragma unroll
                for (int i = 0; i < 4; i++) {
                    uint32_t off = (uint32_t)((row + i * 16) * PAD + col) * 2;
                    uint32_t r[4];
                    ldx4(r, sb + OFF_BH + off);
                    b_hi[i*2][0] = r[0]; b_hi[i*2][1] = r[1];
                    b_hi[i*2+1][0] = r[2]; b_hi[i*2+1][1] = r[3];
                    ldx4(r, sb + OFF_BL + off);
                    b_lo[i*2][0] = r[0]; b_lo[i*2][1] = r[1];
                    b_lo[i*2+1][0] = r[2]; b_lo[i*2+1][1] = r[3];
                }
            }
            #pragma unroll
            for (int mt = 0; mt < 2; mt++)
                #pragma unroll
                for (int nt = 0; nt < 8; nt++) {
                    mma_bf16(acc[mt][nt], a_hi[mt], b_hi[nt]);   // Ah*Bh
                    mma_bf16(acc[mt][nt], a_hi[mt], b_lo[nt]);   // Ah*Bl
                    mma_bf16(acc[mt][nt], a_lo[mt], b_hi[nt]);   // Al*Bh
                }
        }
        if (kc + 1 < nchunks) SSTORE(cur ^ 1);
        __syncthreads();
    }

    // ---- epilogue ----
    int crow = m0 + wm * 32 + (lane >> 2);
    int ccol = n0c + wn * 64 + (lane & 3) * 2;
    #pragma unroll
    for (int mt = 0; mt < 2; mt++) {
        #pragma unroll
        for (int nt = 0; nt < 8; nt++) {
            float* cp = Cc + (size_t)(crow + mt * 16) * CC + ccol + nt * 8;
            *(float2*)cp              = make_float2(acc[mt][nt][0], acc[mt][nt][1]);
            *(float2*)(cp + 8 * CC)   = make_float2(acc[mt][nt][2], acc[mt][nt][3]);
        }
    }
#undef GLOAD
#undef SSTORE
}

// ---------------- SpMM (bias dropped: BN is invariant to per-channel constants) ----------------
__global__ void k_spmm(const float* __restrict__ hw, float* __restrict__ agg, int Gc) {
    int wid  = (blockIdx.x*blockDim.x + threadIdx.x) >> 5;
    int lane = threadIdx.x & 31;
    if (wid >= Gc * LL) return;
    int g = wid / LL, dst = wid - g * LL;
    const float* rowbase = hw + (size_t)g * LL * CC;
    float acc[8];
    {
        float w = g_selfw[dst];
        const float4* r = (const float4*)(rowbase + (size_t)dst * CC);
        float4 v0 = r[lane], v1 = r[lane + 32];
        acc[0] = w * v0.x; acc[1] = w * v0.y; acc[2] = w * v0.z; acc[3] = w * v0.w;
        acc[4] = w * v1.x; acc[5] = w * v1.y; acc[6] = w * v1.z; acc[7] = w * v1.w;
    }
    int p0 = g_rowptr[dst], p1 = g_rowptr[dst + 1];
    for (int p = p0; p < p1; p++) {
        int s = g_col[p];
        float w = g_w[p];
        const float4* r = (const float4*)(rowbase + (size_t)s * CC);
        float4 v0 = r[lane], v1 = r[lane + 32];
        acc[0] = fmaf(w, v0.x, acc[0]); acc[1] = fmaf(w, v0.y, acc[1]);
        acc[2] = fmaf(w, v0.z, acc[2]); acc[3] = fmaf(w, v0.w, acc[3]);
        acc[4] = fmaf(w, v1.x, acc[4]); acc[5] = fmaf(w, v1.y, acc[5]);
        acc[6] = fmaf(w, v1.z, acc[6]); acc[7] = fmaf(w, v1.w, acc[7]);
    }
    float4* o = (float4*)(agg + ((size_t)g * LL + dst) * CC);
    o[lane]      = make_float4(acc[0], acc[1], acc[2], acc[3]);
    o[lane + 32] = make_float4(acc[4], acc[5], acc[6], acc[7]);
}

// ---------------- BN stats (two-stage deterministic) ----------------
__global__ void k_bnpart(const float* __restrict__ a, float* __restrict__ part, int M) {
    int c = threadIdx.x;
    int rpb = M / PARTS;
    int r0 = blockIdx.x * rpb;
    float s = 0.f, q = 0.f;
    for (int r = 0; r < rpb; r++) {
        float v = a[(size_t)(r0 + r) * CC + c];
        s += v;
        q = fmaf(v, v, q);
    }
    part[blockIdx.x * (2*CC) + c]      = s;
    part[blockIdx.x * (2*CC) + CC + c] = q;
}

__global__ void k_bnfinal(const float* __restrict__ part,
                          const float* __restrict__ gamma, const float* __restrict__ beta,
                          float* __restrict__ scale, float* __restrict__ shift, int M) {
    int c = threadIdx.x;
    float s = 0.f, q = 0.f;
    for (int p = 0; p < PARTS; p++) {
        s += part[p * (2*CC) + c];
        q += part[p * (2*CC) + CC + c];
    }
    float invM = 1.0f / (float)M;
    float mean = s * invM;
    float var  = q * invM - mean * mean;
    float sc = gamma[c] * rsqrtf(var + 1e-5f);
    scale[c] = sc;
    shift[c] = beta[c] - mean * sc;
}

// ---------------- fused BN-apply + branch add + ReLU + pool (layers 0,1) ----------------
// one thread per (b, l, c4); loops all 8 n-copies, writes bufX and pooled max.
__global__ void k_finalize_pool(float* __restrict__ outp, float* __restrict__ xpo) {
    size_t idx = (size_t)blockIdx.x * blockDim.x + threadIdx.x;   // BB*LL*64
    size_t c4 = idx & 63;
    size_t bl = idx >> 6;               // b*LL + l
    size_t b  = bl >> 11;               // LL = 2048
    size_t l  = bl & 2047;
    float4 s1 = ((const float4*)g_scale1)[c4], h1 = ((const float4*)g_shift1)[c4];
    float4 s2 = ((const float4*)g_scale2)[c4], h2 = ((const float4*)g_shift2)[c4];
    float4 as = ((const float4*)g_aggs)[idx];
    float4 x2;
    x2.x = fmaf(as.x, s2.x, h2.x); x2.y = fmaf(as.y, s2.y, h2.y);
    x2.z = fmaf(as.z, s2.z, h2.z); x2.w = fmaf(as.w, s2.w, h2.w);
    float4 mx = make_float4(-FLT_MAX, -FLT_MAX, -FLT_MAX, -FLT_MAX);
    #pragma unroll
    for (int n = 0; n < 8; n++) {
        size_t off = (((b * 8 + n) * LL + l) << 6) + c4;
        float4 a = ((const float4*)g_bufAG)[off];
        float4 o;
        o.x = fmaxf(fmaf(a.x, s1.x, h1.x) + x2.x, 0.f);
        o.y = fmaxf(fmaf(a.y, s1.y, h1.y) + x2.y, 0.f);
        o.z = fmaxf(fmaf(a.z, s1.z, h1.z) + x2.z, 0.f);
        o.w = fmaxf(fmaf(a.w, s1.w, h1.w) + x2.w, 0.f);
        ((float4*)outp)[off] = o;
        mx.x = fmaxf(mx.x, o.x); mx.y = fmaxf(mx.y, o.y);
        mx.z = fmaxf(mx.z, o.z); mx.w = fmaxf(mx.w, o.w);
    }
    ((float4*)xpo)[idx] = mx;
}

// ---------------- fused last-layer finalize + transpose to [g][c][l] ----------------
__global__ void k_finalize_t(float* __restrict__ out) {
    __shared__ float tile[32][33];
    int g = blockIdx.z;
    int b = g >> 3;
    int l0 = blockIdx.x * 32, c0 = blockIdx.y * 32;
    int tx = threadIdx.x, ty = threadIdx.y;
    int ch = c0 + tx;
    float s1 = g_scale1[ch], h1 = g_shift1[ch];
    float s2 = g_scale2[ch], h2 = g_shift2[ch];
    #pragma unroll
    for (int i = ty; i < 32; i += 8) {
        float a  = g_bufAG[((size_t)g * LL + l0 + i) * CC + ch];
        float as = g_aggs [((size_t)b * LL + l0 + i) * CC + ch];
        tile[i][tx] = fmaxf(fmaf(a, s1, h1) + fmaf(as, s2, h2), 0.f);
    }
    __syncthreads();
    #pragma unroll
    for (int i = ty; i < 32; i += 8)
        out[((size_t)g * CC + c0 + i) * LL + l0 + tx] = tile[tx][i];
}

// ---------------- launch ----------------
extern "C" void kernel_launch(void* const* d_in, const int* in_sizes, int n_in,
                              void* d_out, int out_size) {
    const float* x  = (const float*)d_in[0];
    const int*   ei = (const int*)  d_in[1];
    const float* W [3] = {(const float*)d_in[2],  (const float*)d_in[4],  (const float*)d_in[6]};
    const float* Ws[3] = {(const float*)d_in[8],  (const float*)d_in[10], (const float*)d_in[12]};
    const float* ga[3] = {(const float*)d_in[14], (const float*)d_in[16], (const float*)d_in[18]};
    const float* be[3] = {(const float*)d_in[15], (const float*)d_in[17], (const float*)d_in[19]};
    const float* gs[3] = {(const float*)d_in[20], (const float*)d_in[22], (const float*)d_in[24]};
    const float* bes[3]= {(const float*)d_in[21], (const float*)d_in[23], (const float*)d_in[25]};

    float *bufX, *bufHW, *bufAG, *xp, *hws, *aggs, *part, *parts, *sc1, *sh1, *sc2, *sh2;
    __nv_bfloat16 *wt_hi, *wt_lo, *wts_hi, *wts_lo;
    cudaGetSymbolAddress((void**)&bufX,  g_bufX);
    cudaGetSymbolAddress((void**)&bufHW, g_bufHW);
    cudaGetSymbolAddress((void**)&bufAG, g_bufAG);
    cudaGetSymbolAddress((void**)&xp,    g_xp);
    cudaGetSymbolAddress((void**)&hws,   g_hws);
    cudaGetSymbolAddress((void**)&aggs,  g_aggs);
    cudaGetSymbolAddress((void**)&part,  g_part);
    cudaGetSymbolAddress((void**)&parts, g_parts);
    cudaGetSymbolAddress((void**)&sc1,   g_scale1);
    cudaGetSymbolAddress((void**)&sh1,   g_shift1);
    cudaGetSymbolAddress((void**)&sc2,   g_scale2);
    cudaGetSymbolAddress((void**)&sh2,   g_shift2);
    cudaGetSymbolAddress((void**)&wt_hi,  g_wt_hi);
    cudaGetSymbolAddress((void**)&wt_lo,  g_wt_lo);
    cudaGetSymbolAddress((void**)&wts_hi, g_wts_hi);
    cudaGetSymbolAddress((void**)&wts_lo, g_wts_lo);

    static int smem_set = 0;
    cudaFuncSetAttribute(k_gemm_mma, cudaFuncAttributeMaxDynamicSharedMemorySize, 2 * STAGE);
    (void)smem_set;

    // graph preprocessing (deterministic)
    k_zero_graph<<<(LL + 255) / 256, 256>>>();
    k_deg<<<EE / 256, 256>>>(ei);
    k_dis<<<(LL + 255) / 256, 256>>>();
    k_scan<<<1, 1024>>>();
    k_fill<<<LL / 8, 256>>>(ei);

    k_transpose_in<<<dim3(LL / 32, C0 / 32, GG), dim3(32, 8)>>>(x);
    k_pool<<<(BB * LL * C0 + 255) / 256, 256>>>(C0);   // layer-0 pooled input

    int Cin = C0;
    for (int layer = 0; layer < 3; layer++) {
        k_wsplit<<<(Cin * CC + 255) / 256, 256>>>(W[layer],  wt_hi,  wt_lo,  Cin);
        k_wsplit<<<(Cin * CC + 255) / 256, 256>>>(Ws[layer], wts_hi, wts_lo, Cin);
        k_gemm_mma<<<dim3(2, GG * LL / 128), 256, 2 * STAGE>>>(bufX, wt_hi, wt_lo, bufHW, Cin);
        k_gemm_mma<<<dim3(2, BB * LL / 128), 256, 2 * STAGE>>>(xp, wts_hi, wts_lo, hws, Cin);
        k_spmm<<<GG * LL / 8, 256>>>(bufHW, bufAG, GG);
        k_spmm<<<BB * LL / 8, 256>>>(hws, aggs, BB);
        k_bnpart<<<PARTS, 256>>>(bufAG, part, GG * LL);
        k_bnpart<<<PARTS, 256>>>(aggs, parts, BB * LL);
        k_bnfinal<<<1, 256>>>(part,  ga[layer], be[layer],  sc1, sh1, GG * LL);
        k_bnfinal<<<1, 256>>>(parts, gs[layer], bes[layer], sc2, sh2, BB * LL);
        if (layer < 2) {
            k_finalize_pool<<<(BB * LL * 64) / 256, 256>>>(bufX, xp);
        } else {
            k_finalize_t<<<dim3(LL / 32, CC / 32, GG), dim3(32, 8)>>>((float*)d_out);
        }
        Cin = CC;
    }
}

// round 5
// speedup vs baseline: 1.5874x; 1.0227x over previous
#include <cuda_runtime.h>
#include <cuda_bf16.h>
#include <cstdint>
#include <cfloat>

// Problem constants
#define BB 4
#define NN 8
#define GG 32          // BB*NN
#define LL 2048
#define EE 16384
#define C0 128
#define CC 256
#define PAD 40         // padded SMEM row length in bf16 elems (80 bytes)

// ---------------- scratch (device globals; no allocation allowed) ----------------
__device__ __align__(16) float g_bufHW[(size_t)GG*LL*CC];   // gemm output  [g][l][co]
__device__ __align__(16) float g_bufAG[(size_t)GG*LL*CC];   // aggregated   [g][l][co]
__device__ __align__(16) float g_hws  [(size_t)BB*LL*CC];
__device__ __align__(16) float g_aggs [(size_t)BB*LL*CC];

// split-bf16 activations [g][l][c]
__device__ __align__(16) __nv_bfloat16 g_xhi [(size_t)GG*LL*CC];
__device__ __align__(16) __nv_bfloat16 g_xlo [(size_t)GG*LL*CC];
__device__ __align__(16) __nv_bfloat16 g_xphi[(size_t)BB*LL*CC];
__device__ __align__(16) __nv_bfloat16 g_xplo[(size_t)BB*LL*CC];

__device__ float g_deg[LL];
__device__ float g_dis[LL];
__device__ float g_selfw[LL];
__device__ int   g_cnt[LL];
__device__ int   g_rowptr[LL+1];
__device__ int   g_col[EE];
__device__ float g_w[EE];

// BN partials: per-spmm-block (sum, sumsq) x 256 channels
__device__ __align__(16) float g_part2 [(size_t)(GG*LL/8)*2*CC];
__device__ __align__(16) float g_parts2[(size_t)(BB*LL/8)*2*CC];
__device__ __align__(16) float g_scale1[CC], g_shift1[CC], g_scale2[CC], g_shift2[CC];

// bf16-split, transposed weights: [N=256][K] row-major
__device__ __align__(16) __nv_bfloat16 g_wt_hi [CC*CC];
__device__ __align__(16) __nv_bfloat16 g_wt_lo [CC*CC];
__device__ __align__(16) __nv_bfloat16 g_wts_hi[CC*CC];
__device__ __align__(16) __nv_bfloat16 g_wts_lo[CC*CC];

// ---------------- helpers ----------------
__device__ __forceinline__ uint32_t smem_u32(const void* p) {
    uint32_t a;
    asm("{ .reg .u64 t; cvta.to.shared.u64 t, %1; cvt.u32.u64 %0, t; }" : "=r"(a) : "l"(p));
    return a;
}
__device__ __forceinline__ void ldx4(uint32_t* r, uint32_t addr) {
    asm volatile("ldmatrix.sync.aligned.m8n8.x4.shared.b16 {%0,%1,%2,%3}, [%4];"
        : "=r"(r[0]), "=r"(r[1]), "=r"(r[2]), "=r"(r[3]) : "r"(addr));
}
__device__ __forceinline__ void mma_bf16(float* c, const uint32_t* a, const uint32_t* b) {
    asm volatile(
        "mma.sync.aligned.m16n8k16.row.col.f32.bf16.bf16.f32 "
        "{%0,%1,%2,%3}, {%4,%5,%6,%7}, {%8,%9}, {%0,%1,%2,%3};"
        : "+f"(c[0]), "+f"(c[1]), "+f"(c[2]), "+f"(c[3])
        : "r"(a[0]), "r"(a[1]), "r"(a[2]), "r"(a[3]), "r"(b[0]), "r"(b[1]));
}
__device__ __forceinline__ uint32_t bpack(__nv_bfloat16 a, __nv_bfloat16 b) {
    __nv_bfloat162 t;
    t.x = a; t.y = b;
    return *reinterpret_cast<uint32_t*>(&t);
}

// ---------------- graph preprocessing ----------------
__global__ void k_zero_graph() {
    int i = blockIdx.x*blockDim.x + threadIdx.x;
    if (i < LL) { g_deg[i] = 0.f; g_cnt[i] = 0; }
}

__global__ void k_deg(const int* __restrict__ ei) {
    int e = blockIdx.x*blockDim.x + threadIdx.x;
    if (e < EE) {
        int dst = ei[EE + e];
        atomicAdd(&g_deg[dst], 1.0f);
        atomicAdd(&g_cnt[dst], 1);
    }
}

__global__ void k_dis() {
    int i = blockIdx.x*blockDim.x + threadIdx.x;
    if (i < LL) {
        float d = g_deg[i] + 2.0f;
        float r = rsqrtf(d);
        g_dis[i] = r;
        g_selfw[i] = 2.0f * r * r;
    }
}

__global__ void k_scan() {
    __shared__ int s[2][LL];
    int t = threadIdx.x;
    s[0][t]        = g_cnt[t];
    s[0][t + 1024] = g_cnt[t + 1024];
    __syncthreads();
    int cur = 0;
    for (int off = 1; off < LL; off <<= 1) {
        int nxt = cur ^ 1;
        for (int i = t; i < LL; i += 1024) {
            int v = s[cur][i];
            if (i >= off) v += s[cur][i - off];
            s[nxt][i] = v;
        }
        __syncthreads();
        cur = nxt;
    }
    for (int i = t; i < LL; i += 1024) g_rowptr[i + 1] = s[cur][i];
    if (t == 0) g_rowptr[0] = 0;
}

__global__ void k_fill(const int* __restrict__ ei) {
    int wid  = (blockIdx.x*blockDim.x + threadIdx.x) >> 5;
    int lane = threadIdx.x & 31;
    if (wid >= LL) return;
    int node = wid;
    int base = g_rowptr[node];
    float dn = g_dis[node];
    int count = 0;
    for (int e0 = 0; e0 < EE; e0 += 32) {
        int e = e0 + lane;
        int d = ei[EE + e];
        bool m = (d == node);
        unsigned mask = __ballot_sync(0xffffffffu, m);
        if (m) {
            int rank = __popc(mask & ((1u << lane) - 1u));
            int s = ei[e];
            g_col[base + count + rank] = s;
            g_w  [base + count + rank] = g_dis[s] * dn;
        }
        count += __popc(mask);
    }
}

// ---------------- input transpose: x [g][c][l] fp32 -> xhi/xlo [g][l][c] ----------------
__global__ void k_transpose_in(const float* __restrict__ x) {
    __shared__ float tile[32][33];
    int g = blockIdx.z;
    int l0 = blockIdx.x * 32, c0 = blockIdx.y * 32;
    int tx = threadIdx.x, ty = threadIdx.y;
    const float* src = x + (size_t)g * C0 * LL;
    #pragma unroll
    for (int i = ty; i < 32; i += 8)
        tile[i][tx] = src[(size_t)(c0 + i) * LL + l0 + tx];
    __syncthreads();
    size_t dbase = (size_t)g * LL * C0;
    #pragma unroll
    for (int i = ty; i < 32; i += 8) {
        float v = tile[tx][i];
        __nv_bfloat16 h = __float2bfloat16(v);
        size_t o = dbase + (size_t)(l0 + i) * C0 + c0 + tx;
        g_xhi[o] = h;
        g_xlo[o] = __float2bfloat16(v - __bfloat162float(h));
    }
}

// ---------------- layer-0 pool: max over n from split-bf16, output split-bf16 ----------------
__global__ void k_pool0() {
    int idx = blockIdx.x*blockDim.x + threadIdx.x;    // bf16x2 pairs
    int per2 = LL * C0 / 2;
    int tot = BB * per2;
    if (idx >= tot) return;
    int b = idx / per2;
    int rem = idx - b * per2;
    size_t base = (size_t)b * NN * per2 + rem;
    const __nv_bfloat162* xh2 = (const __nv_bfloat162*)g_xhi;
    const __nv_bfloat162* xl2 = (const __nv_bfloat162*)g_xlo;
    float mx = -FLT_MAX, my = -FLT_MAX;
    #pragma unroll
    for (int n = 0; n < NN; n++) {
        __nv_bfloat162 h = xh2[base + (size_t)n * per2];
        __nv_bfloat162 l = xl2[base + (size_t)n * per2];
        mx = fmaxf(mx, __bfloat162float(h.x) + __bfloat162float(l.x));
        my = fmaxf(my, __bfloat162float(h.y) + __bfloat162float(l.y));
    }
    __nv_bfloat16 hx = __float2bfloat16(mx), hy = __float2bfloat16(my);
    __nv_bfloat162 oh, ol;
    oh.x = hx; oh.y = hy;
    ol.x = __float2bfloat16(mx - __bfloat162float(hx));
    ol.y = __float2bfloat16(my - __bfloat162float(hy));
    ((__nv_bfloat162*)g_xphi)[idx] = oh;
    ((__nv_bfloat162*)g_xplo)[idx] = ol;
}

// ---------------- weight transpose + bf16 split ----------------
__global__ void k_wsplit(const float* __restrict__ W,
                         __nv_bfloat16* __restrict__ wt_hi,
                         __nv_bfloat16* __restrict__ wt_lo, int K) {
    int idx = blockIdx.x*blockDim.x + threadIdx.x;   // over K*256, k-major
    if (idx >= K * CC) return;
    int k = idx >> 8, n = idx & 255;
    float v = W[idx];  // W[k][n]
    __nv_bfloat16 h = __float2bfloat16(v);
    float lo = v - __bfloat162float(h);
    wt_hi[(size_t)n * K + k] = h;
    wt_lo[(size_t)n * K + k] = __float2bfloat16(lo);
}

// ---------------- HMMA split-bf16 GEMM, double-buffered, pre-split A ----------------
// C[M,256] = A * Wt^T. A hi/lo bf16 [M][K]; Wt hi/lo bf16 [256][K].
// grid (2, M/128), 256 threads. CTA tile 128x128, warp tile 32x64, K-chunk 32.
#define OFF_AH 0
#define OFF_AL 10240
#define OFF_BH 20480
#define OFF_BL 30720
#define STAGE  40960

__global__ __launch_bounds__(256, 1)
void k_gemm_mma(const __nv_bfloat16* __restrict__ Ahi,
                const __nv_bfloat16* __restrict__ Alo,
                const __nv_bfloat16* __restrict__ Bhg,
                const __nv_bfloat16* __restrict__ Blg,
                float* __restrict__ Cc, int K) {
    extern __shared__ char sm[];
    int tid  = threadIdx.x;
    int lane = tid & 31;
    int warp = tid >> 5;
    int wm = warp & 3;           // m 32-block
    int wn = warp >> 2;          // n 64-block
    int n0c = blockIdx.x * 128;
    int m0  = blockIdx.y * 128;

    float acc[2][8][4];
    #pragma unroll
    for (int i = 0; i < 2; i++)
        #pragma unroll
        for (int j = 0; j < 8; j++)
            #pragma unroll
            for (int t = 0; t < 4; t++) acc[i][j][t] = 0.f;

    int lr = tid >> 1;            // staging row 0..127
    int lc = (tid & 1) << 4;      // col 0 / 16
    uint32_t so = (uint32_t)(lr * PAD + lc) * 2;   // byte offset within a matrix

    uint4 ahR0, ahR1, alR0, alR1, bhR0, bhR1, blR0, blR1;

    int nchunks = K >> 5;

#define GLOAD(kc) do { \
    const __nv_bfloat16* ahp = Ahi + (size_t)(m0 + lr) * K + (kc) * 32 + lc; \
    const __nv_bfloat16* alp = Alo + (size_t)(m0 + lr) * K + (kc) * 32 + lc; \
    ahR0 = *(const uint4*)(ahp); ahR1 = *(const uint4*)(ahp + 8); \
    alR0 = *(const uint4*)(alp); alR1 = *(const uint4*)(alp + 8); \
    const __nv_bfloat16* bhp = Bhg + (size_t)(n0c + lr) * K + (kc) * 32 + lc; \
    const __nv_bfloat16* blp = Blg + (size_t)(n0c + lr) * K + (kc) * 32 + lc; \
    bhR0 = *(const uint4*)(bhp); bhR1 = *(const uint4*)(bhp + 8); \
    blR0 = *(const uint4*)(blp); blR1 = *(const uint4*)(blp + 8); \
} while (0)

#define SSTORE(stg) do { \
    char* sb = sm + (stg) * STAGE; \
    *(uint4*)(sb + OFF_AH + so)      = ahR0; \
    *(uint4*)(sb + OFF_AH + so + 16) = ahR1; \
    *(uint4*)(sb + OFF_AL + so)      = alR0; \
    *(uint4*)(sb + OFF_AL + so + 16) = alR1; \
    *(uint4*)(sb + OFF_BH + so)      = bhR0; \
    *(uint4*)(sb + OFF_BH + so + 16) = bhR1; \
    *(uint4*)(sb + OFF_BL + so)      = blR0; \
    *(uint4*)(sb + OFF_BL + so + 16) = blR1; \
} while (0)

    // prologue
    GLOAD(0);
    SSTORE(0);
    __syncthreads();

    for (int kc = 0; kc < nchunks; kc++) {
        int cur = kc & 1;
        if (kc + 1 < nchunks) GLOAD(kc + 1);

        uint32_t sb = smem_u32(sm + cur * STAGE);
        #pragma unroll
        for (int ks = 0; ks < 2; ks++) {
            uint32_t a_hi[2][4], a_lo[2][4];
            {
                int row = wm * 32 + (lane & 15);
                int col = ks * 16 + (lane >> 4) * 8;
                #pragma unroll
                for (int mt = 0; mt < 2; mt++) {
                    uint32_t off = (uint32_t)((row + mt * 16) * PAD + col) * 2;
                    ldx4(a_hi[mt], sb + OFF_AH + off);
                    ldx4(a_lo[mt], sb + OFF_AL + off);
                }
            }
            uint32_t b_hi[8][2], b_lo[8][2];
            {
                int row = wn * 64 + (lane & 7) + ((lane >> 4) << 3);
                int col = ks * 16 + ((lane >> 3) & 1) * 8;
                #pragma unroll
                for (int i = 0; i < 4; i++) {
                    uint32_t off = (uint32_t)((row + i * 16) * PAD + col) * 2;
                    uint32_t r[4];
                    ldx4(r, sb + OFF_BH + off);
                    b_hi[i*2][0] = r[0]; b_hi[i*2][1] = r[1];
                    b_hi[i*2+1][0] = r[2]; b_hi[i*2+1][1] = r[3];
                    ldx4(r, sb + OFF_BL + off);
                    b_lo[i*2][0] = r[0]; b_lo[i*2][1] = r[1];
                    b_lo[i*2+1][0] = r[2]; b_lo[i*2+1][1] = r[3];
                }
            }
            #pragma unroll
            for (int mt = 0; mt < 2; mt++)
                #pragma unroll
                for (int nt = 0; nt < 8; nt++) {
                    mma_bf16(acc[mt][nt], a_hi[mt], b_hi[nt]);   // Ah*Bh
                    mma_bf16(acc[mt][nt], a_hi[mt], b_lo[nt]);   // Ah*Bl
                    mma_bf16(acc[mt][nt], a_lo[mt], b_hi[nt]);   // Al*Bh
                }
        }
        if (kc + 1 < nchunks) SSTORE(cur ^ 1);
        __syncthreads();
    }

    // ---- epilogue ----
    int crow = m0 + wm * 32 + (lane >> 2);
    int ccol = n0c + wn * 64 + (lane & 3) * 2;
    #pragma unroll
    for (int mt = 0; mt < 2; mt++) {
        #pragma unroll
        for (int nt = 0; nt < 8; nt++) {
            float* cp = Cc + (size_t)(crow + mt * 16) * CC + ccol + nt * 8;
            *(float2*)cp              = make_float2(acc[mt][nt][0], acc[mt][nt][1]);
            *(float2*)(cp + 8 * CC)   = make_float2(acc[mt][nt][2], acc[mt][nt][3]);
        }
    }
#undef GLOAD
#undef SSTORE
}

// ---------------- SpMM + fused BN partial stats ----------------
// 256 threads = 8 warps = 8 dst rows per block; emits per-block (sum, sumsq)[256].
__global__ void k_spmm(const float* __restrict__ hw, float* __restrict__ agg,
                       float* __restrict__ part2, int Gc) {
    __shared__ float red[8][CC];
    int tid  = threadIdx.x;
    int warp = tid >> 5;
    int lane = tid & 31;
    int wid  = blockIdx.x * 8 + warp;
    int g = wid / LL, dst = wid - g * LL;
    const float* rowbase = hw + (size_t)g * LL * CC;
    float acc[8];
    {
        float w = g_selfw[dst];
        const float4* r = (const float4*)(rowbase + (size_t)dst * CC);
        float4 v0 = r[lane], v1 = r[lane + 32];
        acc[0] = w * v0.x; acc[1] = w * v0.y; acc[2] = w * v0.z; acc[3] = w * v0.w;
        acc[4] = w * v1.x; acc[5] = w * v1.y; acc[6] = w * v1.z; acc[7] = w * v1.w;
    }
    int p0 = g_rowptr[dst], p1 = g_rowptr[dst + 1];
    for (int p = p0; p < p1; p++) {
        int s = g_col[p];
        float w = g_w[p];
        const float4* r = (const float4*)(rowbase + (size_t)s * CC);
        float4 v0 = r[lane], v1 = r[lane + 32];
        acc[0] = fmaf(w, v0.x, acc[0]); acc[1] = fmaf(w, v0.y, acc[1]);
        acc[2] = fmaf(w, v0.z, acc[2]); acc[3] = fmaf(w, v0.w, acc[3]);
        acc[4] = fmaf(w, v1.x, acc[4]); acc[5] = fmaf(w, v1.y, acc[5]);
        acc[6] = fmaf(w, v1.z, acc[6]); acc[7] = fmaf(w, v1.w, acc[7]);
    }
    float4* o = (float4*)(agg + ((size_t)g * LL + dst) * CC);
    o[lane]      = make_float4(acc[0], acc[1], acc[2], acc[3]);
    o[lane + 32] = make_float4(acc[4], acc[5], acc[6], acc[7]);
    // BN partials
    *(float4*)&red[warp][lane * 4]       = make_float4(acc[0], acc[1], acc[2], acc[3]);
    *(float4*)&red[warp][128 + lane * 4] = make_float4(acc[4], acc[5], acc[6], acc[7]);
    __syncthreads();
    float s = 0.f, q = 0.f;
    #pragma unroll
    for (int w = 0; w < 8; w++) {
        float v = red[w][tid];
        s += v;
        q = fmaf(v, v, q);
    }
    part2[(size_t)blockIdx.x * (2*CC) + tid]      = s;
    part2[(size_t)blockIdx.x * (2*CC) + CC + tid] = q;
}

// ---------------- BN reduce: one block per channel, fixed-tree (deterministic) ----------------
__global__ void k_bnreduce(const float* __restrict__ part, int nblocks,
                           const float* __restrict__ gamma, const float* __restrict__ beta,
                           float* __restrict__ scale, float* __restrict__ shift, int M) {
    __shared__ float ss[256], sq[256];
    int c = blockIdx.x, t = threadIdx.x;
    float s = 0.f, q = 0.f;
    for (int p = t; p < nblocks; p += 256) {
        s += part[(size_t)p * (2*CC) + c];
        q += part[(size_t)p * (2*CC) + CC + c];
    }
    ss[t] = s; sq[t] = q;
    __syncthreads();
    for (int o = 128; o > 0; o >>= 1) {
        if (t < o) { ss[t] += ss[t + o]; sq[t] += sq[t + o]; }
        __syncthreads();
    }
    if (t == 0) {
        float invM = 1.0f / (float)M;
        float mean = ss[0] * invM;
        float var  = sq[0] * invM - mean * mean;
        float sc = gamma[c] * rsqrtf(var + 1e-5f);
        scale[c] = sc;
        shift[c] = beta[c] - mean * sc;
    }
}

// ---------------- fused BN-apply + branch add + ReLU + pool + bf16-split (layers 0,1) ----------------
__global__ void k_finalize_pool() {
    size_t idx = (size_t)blockIdx.x * blockDim.x + threadIdx.x;   // BB*LL*64
    size_t c4 = idx & 63;
    size_t bl = idx >> 6;               // b*LL + l
    size_t b  = bl >> 11;               // LL = 2048
    size_t l  = bl & 2047;
    float4 s1 = ((const float4*)g_scale1)[c4], h1 = ((const float4*)g_shift1)[c4];
    float4 s2 = ((const float4*)g_scale2)[c4], h2 = ((const float4*)g_shift2)[c4];
    float4 as = ((const float4*)g_aggs)[idx];
    float4 x2;
    x2.x = fmaf(as.x, s2.x, h2.x); x2.y = fmaf(as.y, s2.y, h2.y);
    x2.z = fmaf(as.z, s2.z, h2.z); x2.w = fmaf(as.w, s2.w, h2.w);
    float4 mx = make_float4(0.f, 0.f, 0.f, 0.f);   // ReLU output >= 0
    #pragma unroll
    for (int n = 0; n < 8; n++) {
        size_t off = (((b * 8 + n) * LL + l) << 6) + c4;   // float4 index
        float4 a = ((const float4*)g_bufAG)[off];
        float4 o;
        o.x = fmaxf(fmaf(a.x, s1.x, h1.x) + x2.x, 0.f);
        o.y = fmaxf(fmaf(a.y, s1.y, h1.y) + x2.y, 0.f);
        o.z = fmaxf(fmaf(a.z, s1.z, h1.z) + x2.z, 0.f);
        o.w = fmaxf(fmaf(a.w, s1.w, h1.w) + x2.w, 0.f);
        __nv_bfloat16 hx = __float2bfloat16(o.x), hy = __float2bfloat16(o.y);
        __nv_bfloat16 hz = __float2bfloat16(o.z), hw = __float2bfloat16(o.w);
        uint2 ph = make_uint2(bpack(hx, hy), bpack(hz, hw));
        uint2 pl = make_uint2(
            bpack(__float2bfloat16(o.x - __bfloat162float(hx)),
                  __float2bfloat16(o.y - __bfloat162float(hy))),
            bpack(__float2bfloat16(o.z - __bfloat162float(hz)),
                  __float2bfloat16(o.w - __bfloat162float(hw))));
        ((uint2*)g_xhi)[off] = ph;
        ((uint2*)g_xlo)[off] = pl;
        mx.x = fmaxf(mx.x, o.x); mx.y = fmaxf(mx.y, o.y);
        mx.z = fmaxf(mx.z, o.z); mx.w = fmaxf(mx.w, o.w);
    }
    __nv_bfloat16 hx = __float2bfloat16(mx.x), hy = __float2bfloat16(mx.y);
    __nv_bfloat16 hz = __float2bfloat16(mx.z), hw = __float2bfloat16(mx.w);
    ((uint2*)g_xphi)[idx] = make_uint2(bpack(hx, hy), bpack(hz, hw));
    ((uint2*)g_xplo)[idx] = make_uint2(
        bpack(__float2bfloat16(mx.x - __bfloat162float(hx)),
              __float2bfloat16(mx.y - __bfloat162float(hy))),
        bpack(__float2bfloat16(mx.z - __bfloat162float(hz)),
              __float2bfloat16(mx.w - __bfloat162float(hw))));
}

// ---------------- fused last-layer finalize + transpose to [g][c][l] ----------------
__global__ void k_finalize_t(float* __restrict__ out) {
    __shared__ float tile[32][33];
    int g = blockIdx.z;
    int b = g >> 3;
    int l0 = blockIdx.x * 32, c0 = blockIdx.y * 32;
    int tx = threadIdx.x, ty = threadIdx.y;
    int ch = c0 + tx;
    float s1 = g_scale1[ch], h1 = g_shift1[ch];
    float s2 = g_scale2[ch], h2 = g_shift2[ch];
    #pragma unroll
    for (int i = ty; i < 32; i += 8) {
        float a  = g_bufAG[((size_t)g * LL + l0 + i) * CC + ch];
        float as = g_aggs [((size_t)b * LL + l0 + i) * CC + ch];
        tile[i][tx] = fmaxf(fmaf(a, s1, h1) + fmaf(as, s2, h2), 0.f);
    }
    __syncthreads();
    #pragma unroll
    for (int i = ty; i < 32; i += 8)
        out[((size_t)g * CC + c0 + i) * LL + l0 + tx] = tile[tx][i];
}

// ---------------- launch ----------------
extern "C" void kernel_launch(void* const* d_in, const int* in_sizes, int n_in,
                              void* d_out, int out_size) {
    const float* x  = (const float*)d_in[0];
    const int*   ei = (const int*)  d_in[1];
    const float* W [3] = {(const float*)d_in[2],  (const float*)d_in[4],  (const float*)d_in[6]};
    const float* Ws[3] = {(const float*)d_in[8],  (const float*)d_in[10], (const float*)d_in[12]};
    const float* ga[3] = {(const float*)d_in[14], (const float*)d_in[16], (const float*)d_in[18]};
    const float* be[3] = {(const float*)d_in[15], (const float*)d_in[17], (const float*)d_in[19]};
    const float* gs[3] = {(const float*)d_in[20], (const float*)d_in[22], (const float*)d_in[24]};
    const float* bes[3]= {(const float*)d_in[21], (const float*)d_in[23], (const float*)d_in[25]};

    float *bufHW, *bufAG, *hws, *aggs, *part2, *parts2, *sc1, *sh1, *sc2, *sh2;
    __nv_bfloat16 *wt_hi, *wt_lo, *wts_hi, *wts_lo, *xhi, *xlo, *xphi, *xplo;
    cudaGetSymbolAddress((void**)&bufHW, g_bufHW);
    cudaGetSymbolAddress((void**)&bufAG, g_bufAG);
    cudaGetSymbolAddress((void**)&hws,   g_hws);
    cudaGetSymbolAddress((void**)&aggs,  g_aggs);
    cudaGetSymbolAddress((void**)&part2, g_part2);
    cudaGetSymbolAddress((void**)&parts2,g_parts2);
    cudaGetSymbolAddress((void**)&sc1,   g_scale1);
    cudaGetSymbolAddress((void**)&sh1,   g_shift1);
    cudaGetSymbolAddress((void**)&sc2,   g_scale2);
    cudaGetSymbolAddress((void**)&sh2,   g_shift2);
    cudaGetSymbolAddress((void**)&wt_hi,  g_wt_hi);
    cudaGetSymbolAddress((void**)&wt_lo,  g_wt_lo);
    cudaGetSymbolAddress((void**)&wts_hi, g_wts_hi);
    cudaGetSymbolAddress((void**)&wts_lo, g_wts_lo);
    cudaGetSymbolAddress((void**)&xhi,  g_xhi);
    cudaGetSymbolAddress((void**)&xlo,  g_xlo);
    cudaGetSymbolAddress((void**)&xphi, g_xphi);
    cudaGetSymbolAddress((void**)&xplo, g_xplo);

    cudaFuncSetAttribute(k_gemm_mma, cudaFuncAttributeMaxDynamicSharedMemorySize, 2 * STAGE);

    // graph preprocessing (deterministic)
    k_zero_graph<<<(LL + 255) / 256, 256>>>();
    k_deg<<<EE / 256, 256>>>(ei);
    k_dis<<<(LL + 255) / 256, 256>>>();
    k_scan<<<1, 1024>>>();
    k_fill<<<LL / 8, 256>>>(ei);

    k_transpose_in<<<dim3(LL / 32, C0 / 32, GG), dim3(32, 8)>>>(x);
    k_pool0<<<(BB * LL * C0 / 2 + 255) / 256, 256>>>();

    int Cin = C0;
    for (int layer = 0; layer < 3; layer++) {
        k_wsplit<<<(Cin * CC + 255) / 256, 256>>>(W[layer],  wt_hi,  wt_lo,  Cin);
        k_wsplit<<<(Cin * CC + 255) / 256, 256>>>(Ws[layer], wts_hi, wts_lo, Cin);
        k_gemm_mma<<<dim3(2, GG * LL / 128), 256, 2 * STAGE>>>(xhi, xlo, wt_hi, wt_lo, bufHW, Cin);
        k_gemm_mma<<<dim3(2, BB * LL / 128), 256, 2 * STAGE>>>(xphi, xplo, wts_hi, wts_lo, hws, Cin);
        k_spmm<<<GG * LL / 8, 256>>>(bufHW, bufAG, part2, GG);
        k_spmm<<<BB * LL / 8, 256>>>(hws, aggs, parts2, BB);
        k_bnreduce<<<CC, 256>>>(part2,  GG * LL / 8, ga[layer], be[layer],  sc1, sh1, GG * LL);
        k_bnreduce<<<CC, 256>>>(parts2, BB * LL / 8, gs[layer], bes[layer], sc2, sh2, BB * LL);
        if (layer < 2) {
            k_finalize_pool<<<(BB * LL * 64) / 256, 256>>>();
        } else {
            k_finalize_t<<<dim3(LL / 32, CC / 32, GG), dim3(32, 8)>>>((float*)d_out);
        }
        Cin = CC;
    }
}